// round 7
// baseline (speedup 1.0000x reference)
#include <cuda_runtime.h>
#include <cuda_bf16.h>
#include <cstdint>

// Problem constants
#define BATCH 2
#define SEQ   2048
#define DIM   1024
#define HEADS 16
#define HDIM  64
#define MROWS (BATCH * SEQ)          // 4096
#define QKV_N (3 * DIM)              // 3072

// Scratch (allocation-free rule: __device__ globals)
__device__ float g_qkv [MROWS * QKV_N];   // [4096, 3072]  row-major, col = h*192 + part*64 + d
__device__ float g_attn[MROWS * DIM];     // [4096, 1024]  attention output, col = h*64 + d

// ---- packed fp32x2 helpers (sm_103a FFMA2 path; full fp32 precision) ------
__device__ __forceinline__ uint64_t pk2(float lo, float hi) {
    uint64_t r;
    asm("mov.b64 %0, {%1, %2};" : "=l"(r) : "f"(lo), "f"(hi));
    return r;
}
__device__ __forceinline__ float2 upk2(uint64_t v) {
    float2 f;
    asm("mov.b64 {%0, %1}, %2;" : "=f"(f.x), "=f"(f.y) : "l"(v));
    return f;
}
__device__ __forceinline__ void fma2(uint64_t& d, uint64_t a, uint64_t b) {
    asm("fma.rn.f32x2 %0, %1, %2, %0;" : "+l"(d) : "l"(a), "l"(b));
}
__device__ __forceinline__ void mul2(uint64_t& d, uint64_t c) {
    asm("mul.rn.f32x2 %0, %0, %1;" : "+l"(d) : "l"(c));
}

// ---------------------------------------------------------------------------
// GEMM: C[M,N] = A[M,K] @ W[N,K]^T (+ bias).  128x128x16 tile, 8x8 per thread,
// 2-stage smem double buffering, FFMA2-packed inner loop (acc packed along j).
// ---------------------------------------------------------------------------
__global__ __launch_bounds__(256, 2)
void gemm_nt(float* __restrict__ C, const float* __restrict__ A,
             const float* __restrict__ W, const float* __restrict__ bias,
             int M, int N, int K)
{
    __shared__ float As[2][16][132];
    __shared__ float Bs[2][16][132];

    const int tid = threadIdx.x;
    const int m0 = blockIdx.y * 128;
    const int n0 = blockIdx.x * 128;
    const int tx = tid & 15;          // col group
    const int ty = tid >> 4;          // row group
    const int lr = tid >> 1;          // loader row within tile (0..127)
    const int lc = (tid & 1) * 8;     // loader k-offset (0 or 8)

    const float* Aptr = A + (m0 + lr) * K + lc;
    const float* Wptr = W + (n0 + lr) * K + lc;

    float4 av0 = *(const float4*)(Aptr);
    float4 av1 = *(const float4*)(Aptr + 4);
    float4 wv0 = *(const float4*)(Wptr);
    float4 wv1 = *(const float4*)(Wptr + 4);

    // Stage 0 fill
    As[0][lc + 0][lr] = av0.x; As[0][lc + 1][lr] = av0.y;
    As[0][lc + 2][lr] = av0.z; As[0][lc + 3][lr] = av0.w;
    As[0][lc + 4][lr] = av1.x; As[0][lc + 5][lr] = av1.y;
    As[0][lc + 6][lr] = av1.z; As[0][lc + 7][lr] = av1.w;
    Bs[0][lc + 0][lr] = wv0.x; Bs[0][lc + 1][lr] = wv0.y;
    Bs[0][lc + 2][lr] = wv0.z; Bs[0][lc + 3][lr] = wv0.w;
    Bs[0][lc + 4][lr] = wv1.x; Bs[0][lc + 5][lr] = wv1.y;
    Bs[0][lc + 6][lr] = wv1.z; Bs[0][lc + 7][lr] = wv1.w;
    __syncthreads();

    // acc2[i][jp] packs C columns (2*jp, 2*jp+1) for row i
    uint64_t acc2[8][4];
#pragma unroll
    for (int i = 0; i < 8; ++i)
#pragma unroll
        for (int jp = 0; jp < 4; ++jp) acc2[i][jp] = 0ull;

    const int nslabs = K / 16;
    for (int s = 0; s < nslabs; ++s) {
        const int cur = s & 1;
        const bool has_next = (s + 1 < nslabs);
        if (has_next) {                         // LDG overlaps compute below
            av0 = *(const float4*)(Aptr + (s + 1) * 16);
            av1 = *(const float4*)(Aptr + (s + 1) * 16 + 4);
            wv0 = *(const float4*)(Wptr + (s + 1) * 16);
            wv1 = *(const float4*)(Wptr + (s + 1) * 16 + 4);
        }

#pragma unroll
        for (int kk = 0; kk < 16; ++kk) {
            float a[8], b[8];
            *(float4*)&a[0] = *(const float4*)&As[cur][kk][ty * 4];
            *(float4*)&a[4] = *(const float4*)&As[cur][kk][64 + ty * 4];
            *(float4*)&b[0] = *(const float4*)&Bs[cur][kk][tx * 4];
            *(float4*)&b[4] = *(const float4*)&Bs[cur][kk][64 + tx * 4];

            uint64_t bp0 = pk2(b[0], b[1]);
            uint64_t bp1 = pk2(b[2], b[3]);
            uint64_t bp2 = pk2(b[4], b[5]);
            uint64_t bp3 = pk2(b[6], b[7]);
#pragma unroll
            for (int i = 0; i < 8; ++i) {
                uint64_t ad = pk2(a[i], a[i]);
                fma2(acc2[i][0], ad, bp0);
                fma2(acc2[i][1], ad, bp1);
                fma2(acc2[i][2], ad, bp2);
                fma2(acc2[i][3], ad, bp3);
            }
        }

        if (has_next) {
            const int nxt = cur ^ 1;
            As[nxt][lc + 0][lr] = av0.x; As[nxt][lc + 1][lr] = av0.y;
            As[nxt][lc + 2][lr] = av0.z; As[nxt][lc + 3][lr] = av0.w;
            As[nxt][lc + 4][lr] = av1.x; As[nxt][lc + 5][lr] = av1.y;
            As[nxt][lc + 6][lr] = av1.z; As[nxt][lc + 7][lr] = av1.w;
            Bs[nxt][lc + 0][lr] = wv0.x; Bs[nxt][lc + 1][lr] = wv0.y;
            Bs[nxt][lc + 2][lr] = wv0.z; Bs[nxt][lc + 3][lr] = wv0.w;
            Bs[nxt][lc + 4][lr] = wv1.x; Bs[nxt][lc + 5][lr] = wv1.y;
            Bs[nxt][lc + 6][lr] = wv1.z; Bs[nxt][lc + 7][lr] = wv1.w;
            __syncthreads();
        }
    }

    // Epilogue: rows {ty*4+i, 64+ty*4+i}, cols {jj*64 + tx*4 .. +3}
#pragma unroll
    for (int i = 0; i < 8; ++i) {
        const int r = m0 + ((i < 4) ? (ty * 4 + i) : (64 + ty * 4 + (i - 4)));
#pragma unroll
        for (int jj = 0; jj < 2; ++jj) {
            const int c = n0 + jj * 64 + tx * 4;
            float2 lo = upk2(acc2[i][jj * 2 + 0]);
            float2 hi = upk2(acc2[i][jj * 2 + 1]);
            float4 o;
            o.x = lo.x; o.y = lo.y; o.z = hi.x; o.w = hi.y;
            if (bias) {
                o.x += bias[c + 0]; o.y += bias[c + 1];
                o.z += bias[c + 2]; o.w += bias[c + 3];
            }
            *(float4*)&C[r * N + c] = o;
        }
    }
}

// ---------------------------------------------------------------------------
// Flash attention (causal, scale = 1/HDIM applied to Q at load).
// Block = (q-block of 64 rows) x (b,h). 256 threads = 16x16, 4x4 reg tiles.
// smem: Qs | Ks | Ps | Vs[2], each 64 x 68 floats (87,040 B dynamic).
// Protocol (2 barriers/iter):
//   S-GEMM(Ks) -> softmax -> STS P -> sync1
//   -> STS K(next)/V(next, vbuf^1) + PV(Ps, vbuf) -> sync2
// S-GEMM packs along k (even/odd halves, natural float4 register pairs);
// PV packs along the output dim. All FMA work runs on FFMA2.
// ---------------------------------------------------------------------------
#define SB 68
#define FLASH_SMEM (5 * 64 * SB * 4)

__global__ __launch_bounds__(256, 2)
void flash_kernel(float* __restrict__ O, const float* __restrict__ qkv)
{
    extern __shared__ float sm[];
    float* Qs  = sm;
    float* Ks  = sm + 1 * 64 * SB;
    float* Ps  = sm + 2 * 64 * SB;
    float* Vb0 = sm + 3 * 64 * SB;
    float* Vb1 = sm + 4 * 64 * SB;

    const int tid = threadIdx.x;
    const int tx = tid & 15;
    const int ty = tid >> 4;
    const int qb = (int)gridDim.x - 1 - (int)blockIdx.x;  // LPT: heavy first
    const int bh = blockIdx.y;               // b*16 + h
    const int b  = bh >> 4;
    const int h  = bh & 15;
    const int q0 = qb * 64;
    const int baseQ = (b * SEQ) * QKV_N + h * 192;
    const float scale = 1.0f / (float)HDIM;

    // Load Q tile (pre-scaled)
#pragma unroll
    for (int it = 0; it < 4; ++it) {
        int idx = it * 256 + tid;
        int r = idx >> 4, c4 = (idx & 15) * 4;
        float4 v = *(const float4*)&qkv[baseQ + (q0 + r) * QKV_N + c4];
        v.x *= scale; v.y *= scale; v.z *= scale; v.w *= scale;
        *(float4*)&Qs[r * SB + c4] = v;
    }

    // Prefetch K/V tile 0 into registers, stage into Ks / Vb0
    float4 kreg[4], vreg[4];
#pragma unroll
    for (int it = 0; it < 4; ++it) {
        int idx = it * 256 + tid;
        int r = idx >> 4, c4 = (idx & 15) * 4;
        int grow = baseQ + r * QKV_N;
        kreg[it] = *(const float4*)&qkv[grow + 64  + c4];
        vreg[it] = *(const float4*)&qkv[grow + 128 + c4];
    }
#pragma unroll
    for (int it = 0; it < 4; ++it) {
        int idx = it * 256 + tid;
        int r = idx >> 4, c4 = (idx & 15) * 4;
        *(float4*)&Ks [r * SB + c4] = kreg[it];
        *(float4*)&Vb0[r * SB + c4] = vreg[it];
    }
    __syncthreads();                 // Q, K0, V0 visible

    // accO2[i][ddp]: output dims (2*ddp, 2*ddp+1) within this thread's 4 cols
    uint64_t accO2[4][2];
    float mprev[4], lprev[4];
#pragma unroll
    for (int i = 0; i < 4; ++i) {
        mprev[i] = -1e30f; lprev[i] = 0.f;
        accO2[i][0] = 0ull; accO2[i][1] = 0ull;
    }

    int vcur = 0;
    for (int jb = 0; jb <= qb; ++jb) {
        const bool has_next = (jb < qb);
        float* Vcur = vcur ? Vb1 : Vb0;
        float* Vnxt = vcur ? Vb0 : Vb1;

        // Prefetch next K/V tile into registers; hidden under S + softmax
        if (has_next) {
#pragma unroll
            for (int it = 0; it < 4; ++it) {
                int idx = it * 256 + tid;
                int r = idx >> 4, c4 = (idx & 15) * 4;
                int grow = baseQ + ((jb + 1) * 64 + r) * QKV_N;
                kreg[it] = *(const float4*)&qkv[grow + 64  + c4];
                vreg[it] = *(const float4*)&qkv[grow + 128 + c4];
            }
        }

        // S = Q @ K^T, packed along k: halves = even/odd float2 partial sums.
        // rows r = ty*4+i, cols c = tx + 16*j (strided -> 2-phase LDS floor)
        uint64_t s2[4][4];
#pragma unroll
        for (int i = 0; i < 4; ++i)
#pragma unroll
            for (int j = 0; j < 4; ++j) s2[i][j] = 0ull;

#pragma unroll
        for (int d4 = 0; d4 < 16; ++d4) {
            float4 qv[4], kv[4];
#pragma unroll
            for (int i = 0; i < 4; ++i)
                qv[i] = *(const float4*)&Qs[(ty * 4 + i) * SB + d4 * 4];
#pragma unroll
            for (int j = 0; j < 4; ++j)
                kv[j] = *(const float4*)&Ks[(tx + 16 * j) * SB + d4 * 4];

            uint64_t qlo[4], qhi[4], klo[4], khi[4];
#pragma unroll
            for (int i = 0; i < 4; ++i) {
                qlo[i] = pk2(qv[i].x, qv[i].y);
                qhi[i] = pk2(qv[i].z, qv[i].w);
            }
#pragma unroll
            for (int j = 0; j < 4; ++j) {
                klo[j] = pk2(kv[j].x, kv[j].y);
                khi[j] = pk2(kv[j].z, kv[j].w);
            }
#pragma unroll
            for (int i = 0; i < 4; ++i)
#pragma unroll
                for (int j = 0; j < 4; ++j) {
                    fma2(s2[i][j], qlo[i], klo[j]);
                    fma2(s2[i][j], qhi[i], khi[j]);
                }
        }

        // Horizontal add of packed halves
        float sacc[4][4];
#pragma unroll
        for (int i = 0; i < 4; ++i)
#pragma unroll
            for (int j = 0; j < 4; ++j) {
                float2 f = upk2(s2[i][j]);
                sacc[i][j] = f.x + f.y;
            }

        // Causal mask: only the diagonal kv block needs it
        if (jb == qb) {
#pragma unroll
            for (int i = 0; i < 4; ++i) {
                int rg = ty * 4 + i;
#pragma unroll
                for (int j = 0; j < 4; ++j)
                    if (tx + 16 * j > rg) sacc[i][j] = -1e30f;
            }
        }

        // Online softmax (row group = 16 lanes sharing ty within a warp half)
#pragma unroll
        for (int i = 0; i < 4; ++i) {
            float mx = fmaxf(fmaxf(sacc[i][0], sacc[i][1]),
                             fmaxf(sacc[i][2], sacc[i][3]));
#pragma unroll
            for (int ofs = 1; ofs < 16; ofs <<= 1)
                mx = fmaxf(mx, __shfl_xor_sync(0xffffffffu, mx, ofs));
            float mnew = fmaxf(mprev[i], mx);
            float corr = __expf(mprev[i] - mnew);
            float s = 0.f;
#pragma unroll
            for (int j = 0; j < 4; ++j) {
                float p = __expf(sacc[i][j] - mnew);
                sacc[i][j] = p;
                s += p;
            }
#pragma unroll
            for (int ofs = 1; ofs < 16; ofs <<= 1)
                s += __shfl_xor_sync(0xffffffffu, s, ofs);
            lprev[i] = lprev[i] * corr + s;
            mprev[i] = mnew;
            uint64_t c2 = pk2(corr, corr);
            mul2(accO2[i][0], c2);
            mul2(accO2[i][1], c2);
        }

        // Store P (strided cols, conflict-free scalar STS)
#pragma unroll
        for (int i = 0; i < 4; ++i)
#pragma unroll
            for (int j = 0; j < 4; ++j)
                Ps[(ty * 4 + i) * SB + tx + 16 * j] = sacc[i][j];
        __syncthreads();   // sync1: P visible; Ks fully read; Vnxt free

        // Stage next K/V (drains during PV below)
        if (has_next) {
#pragma unroll
            for (int it = 0; it < 4; ++it) {
                int idx = it * 256 + tid;
                int r = idx >> 4, c4 = (idx & 15) * 4;
                *(float4*)&Ks  [r * SB + c4] = kreg[it];
                *(float4*)&Vnxt[r * SB + c4] = vreg[it];
            }
        }

        // O += P @ V, packed along output dim. rows r = ty*4+i, dims tx*4+..
#pragma unroll
        for (int c4 = 0; c4 < 16; ++c4) {
            float4 pv[4], vv[4];
#pragma unroll
            for (int i = 0; i < 4; ++i)
                pv[i] = *(const float4*)&Ps[(ty * 4 + i) * SB + c4 * 4];
#pragma unroll
            for (int cc = 0; cc < 4; ++cc)
                vv[cc] = *(const float4*)&Vcur[(c4 * 4 + cc) * SB + tx * 4];

            uint64_t vlo[4], vhi[4];
#pragma unroll
            for (int cc = 0; cc < 4; ++cc) {
                vlo[cc] = pk2(vv[cc].x, vv[cc].y);
                vhi[cc] = pk2(vv[cc].z, vv[cc].w);
            }
#pragma unroll
            for (int i = 0; i < 4; ++i) {
                uint64_t p0 = pk2(pv[i].x, pv[i].x);
                uint64_t p1 = pk2(pv[i].y, pv[i].y);
                uint64_t p2 = pk2(pv[i].z, pv[i].z);
                uint64_t p3 = pk2(pv[i].w, pv[i].w);
                fma2(accO2[i][0], p0, vlo[0]); fma2(accO2[i][1], p0, vhi[0]);
                fma2(accO2[i][0], p1, vlo[1]); fma2(accO2[i][1], p1, vhi[1]);
                fma2(accO2[i][0], p2, vlo[2]); fma2(accO2[i][1], p2, vhi[2]);
                fma2(accO2[i][0], p3, vlo[3]); fma2(accO2[i][1], p3, vhi[3]);
            }
        }

        if (has_next) {
            __syncthreads();   // sync2: K/V(next) visible; P reads complete
            vcur ^= 1;
        }
    }

    // Normalize and write O: [b*S + q0 + r, h*64 + tx*4 .. +3]
#pragma unroll
    for (int i = 0; i < 4; ++i) {
        float inv = 1.0f / lprev[i];
        float2 lo = upk2(accO2[i][0]);
        float2 hi = upk2(accO2[i][1]);
        float4 o;
        o.x = lo.x * inv; o.y = lo.y * inv;
        o.z = hi.x * inv; o.w = hi.y * inv;
        int row = b * SEQ + q0 + ty * 4 + i;
        *(float4*)&O[row * DIM + h * HDIM + tx * 4] = o;
    }
}

// ---------------------------------------------------------------------------
extern "C" void kernel_launch(void* const* d_in, const int* in_sizes, int n_in,
                              void* d_out, int out_size)
{
    (void)in_sizes; (void)n_in; (void)out_size;
    const float* x     = (const float*)d_in[0];
    // d_in[1] is the boolean causal mask; it is exactly tril, handled analytically
    const float* w_qkv = (const float*)d_in[2];
    const float* w_out = (const float*)d_in[3];
    const float* b_out = (const float*)d_in[4];
    float* out = (float*)d_out;

    void *qkv_p = nullptr, *attn_p = nullptr;
    cudaGetSymbolAddress(&qkv_p,  g_qkv);
    cudaGetSymbolAddress(&attn_p, g_attn);
    float* qkv  = (float*)qkv_p;
    float* attn = (float*)attn_p;

    cudaFuncSetAttribute(flash_kernel,
                         cudaFuncAttributeMaxDynamicSharedMemorySize, FLASH_SMEM);

    // 1) QKV projection: [4096,1024] @ [3072,1024]^T -> [4096,3072]
    gemm_nt<<<dim3(QKV_N / 128, MROWS / 128), 256>>>(
        qkv, x, w_qkv, nullptr, MROWS, QKV_N, DIM);

    // 2) Causal flash attention -> [4096,1024] (already [B,S,H*hd] layout)
    flash_kernel<<<dim3(SEQ / 64, BATCH * HEADS), 256, FLASH_SMEM>>>(attn, qkv);

    // 3) Output projection + bias: [4096,1024] @ [1024,1024]^T + b
    gemm_nt<<<dim3(DIM / 128, MROWS / 128), 256>>>(
        out, attn, w_out, b_out, MROWS, DIM, DIM);
}

// round 16
// speedup vs baseline: 1.1383x; 1.1383x over previous
#include <cuda_runtime.h>
#include <cuda_bf16.h>
#include <cstdint>

// Problem constants
#define BATCH 2
#define SEQ   2048
#define DIM   1024
#define HEADS 16
#define HDIM  64
#define MROWS (BATCH * SEQ)          // 4096
#define QKV_N (3 * DIM)              // 3072

// Scratch (allocation-free rule: __device__ globals)
__device__ float g_qkv [MROWS * QKV_N];   // fp32 qkv for flash
__device__ float g_attn[MROWS * DIM];     // fp32 attention output
// bf16x3 split operands
__device__ __nv_bfloat16 g_xh [MROWS * DIM],  g_xl [MROWS * DIM];
__device__ __nv_bfloat16 g_ah [MROWS * DIM],  g_al [MROWS * DIM];
__device__ __nv_bfloat16 g_wqh[QKV_N * DIM],  g_wql[QKV_N * DIM];
__device__ __nv_bfloat16 g_woh[DIM * DIM],    g_wol[DIM * DIM];

// ---- packed fp32x2 helpers (FFMA2 path for flash; base-target legal) -------
__device__ __forceinline__ uint64_t pk2(float lo, float hi) {
    uint64_t r; asm("mov.b64 %0, {%1, %2};" : "=l"(r) : "f"(lo), "f"(hi)); return r;
}
__device__ __forceinline__ float2 upk2(uint64_t v) {
    float2 f; asm("mov.b64 {%0, %1}, %2;" : "=f"(f.x), "=f"(f.y) : "l"(v)); return f;
}
__device__ __forceinline__ void fma2(uint64_t& d, uint64_t a, uint64_t b) {
    asm("fma.rn.f32x2 %0, %1, %2, %0;" : "+l"(d) : "l"(a), "l"(b));
}
__device__ __forceinline__ void mul2(uint64_t& d, uint64_t c) {
    asm("mul.rn.f32x2 %0, %0, %1;" : "+l"(d) : "l"(c));
}

// ---- warp-level bf16 HMMA (sm_80-era PTX, valid on compute_103 base) -------
__device__ __forceinline__ void mma16816(float* d, const uint32_t* a,
                                         const uint32_t* b) {
    asm volatile(
        "mma.sync.aligned.m16n8k16.row.col.f32.bf16.bf16.f32 "
        "{%0,%1,%2,%3}, {%4,%5,%6,%7}, {%8,%9}, {%0,%1,%2,%3};"
        : "+f"(d[0]), "+f"(d[1]), "+f"(d[2]), "+f"(d[3])
        : "r"(a[0]), "r"(a[1]), "r"(a[2]), "r"(a[3]), "r"(b[0]), "r"(b[1]));
}

// ===================== fp32 -> bf16 hi/lo split =============================
__global__ void cvt_split(const float* __restrict__ x,
                          __nv_bfloat16* __restrict__ hi,
                          __nv_bfloat16* __restrict__ lo, int n4)
{
    int i = blockIdx.x * blockDim.x + threadIdx.x;
    if (i >= n4) return;
    float4 v = ((const float4*)x)[i];
    __nv_bfloat16 h0 = __float2bfloat16(v.x);
    __nv_bfloat16 h1 = __float2bfloat16(v.y);
    __nv_bfloat16 h2 = __float2bfloat16(v.z);
    __nv_bfloat16 h3 = __float2bfloat16(v.w);
    __nv_bfloat16 l0 = __float2bfloat16(v.x - __bfloat162float(h0));
    __nv_bfloat16 l1 = __float2bfloat16(v.y - __bfloat162float(h1));
    __nv_bfloat16 l2 = __float2bfloat16(v.z - __bfloat162float(h2));
    __nv_bfloat16 l3 = __float2bfloat16(v.w - __bfloat162float(h3));
    ((__nv_bfloat162*)hi)[2*i]   = __nv_bfloat162(h0, h1);
    ((__nv_bfloat162*)hi)[2*i+1] = __nv_bfloat162(h2, h3);
    ((__nv_bfloat162*)lo)[2*i]   = __nv_bfloat162(l0, l1);
    ((__nv_bfloat162*)lo)[2*i+1] = __nv_bfloat162(l2, l3);
}

// ===================== HMMA bf16x3 GEMM =====================================
// C[M,N] = (Ah+Al)[M,K] @ (Bh+Bl)[N,K]^T (+ bias); fp32 accum of
// AhBh + AhBl + AlBh. Block tile 128x128x16, 8 warps (2x4), warp tile 64x32.
// Smem: Ah|Al|Bh|Bl tiles, 128 rows x 16 k at padded stride 24 elements
// (conflict-free for the m16n8k16 fragment access pattern), double-buffered.
#define LDS_P  24                                 // padded stride (elements)
#define MAT_B  (128 * LDS_P * 2)                  // bytes per matrix tile: 6144
#define HOFF_AH 0
#define HOFF_AL (1 * MAT_B)
#define HOFF_BH (2 * MAT_B)
#define HOFF_BL (3 * MAT_B)
#define HSTAGE  (4 * MAT_B)                       // 24576 B per stage
#define HMMA_SMEM (2 * HSTAGE)                    // 49152 B

__global__ __launch_bounds__(256)
void mma_hmma_bf16x3(float* __restrict__ C,
                     const __nv_bfloat16* __restrict__ Ah,
                     const __nv_bfloat16* __restrict__ Al,
                     const __nv_bfloat16* __restrict__ Bh,
                     const __nv_bfloat16* __restrict__ Bl,
                     const float* __restrict__ bias,
                     int M, int N, int K)
{
    extern __shared__ char smem[];
    const int tid = threadIdx.x;
    const int wid = tid >> 5;
    const int lane = tid & 31;
    const int g = lane >> 2;          // 0..7
    const int t = lane & 3;           // 0..3
    const int warp_m = wid & 1;       // 2 warps along M (64 rows each)
    const int warp_n = wid >> 1;      // 4 warps along N (32 cols each)
    const int m0 = blockIdx.y * 128;
    const int n0 = blockIdx.x * 128;

    // Loader coords: r = tid>>1 (0..127), kc = (tid&1)*8 (half-row of 8 bf16)
    const int lr = tid >> 1;
    const int lkc = (tid & 1) * 8;
    const __nv_bfloat16* gAh = Ah + (size_t)(m0 + lr) * K + lkc;
    const __nv_bfloat16* gAl = Al + (size_t)(m0 + lr) * K + lkc;
    const __nv_bfloat16* gBh = Bh + (size_t)(n0 + lr) * K + lkc;
    const __nv_bfloat16* gBl = Bl + (size_t)(n0 + lr) * K + lkc;
    const uint32_t sts_off = (uint32_t)(lr * LDS_P + lkc) * 2;  // bytes

    // Stage 0 fill
    {
        uint4 va_h = *(const uint4*)gAh;
        uint4 va_l = *(const uint4*)gAl;
        uint4 vb_h = *(const uint4*)gBh;
        uint4 vb_l = *(const uint4*)gBl;
        *(uint4*)(smem + HOFF_AH + sts_off) = va_h;
        *(uint4*)(smem + HOFF_AL + sts_off) = va_l;
        *(uint4*)(smem + HOFF_BH + sts_off) = vb_h;
        *(uint4*)(smem + HOFF_BL + sts_off) = vb_l;
    }
    __syncthreads();

    float acc[4][4][4];               // [mt][nt][c0..c3]
#pragma unroll
    for (int mt = 0; mt < 4; ++mt)
#pragma unroll
        for (int nt = 0; nt < 4; ++nt)
#pragma unroll
            for (int c = 0; c < 4; ++c) acc[mt][nt][c] = 0.f;

    const int NS = K / 16;
    for (int s = 0; s < NS; ++s) {
        const int cur = s & 1;
        const bool has_next = (s + 1 < NS);
        uint4 na_h, na_l, nb_h, nb_l;
        if (has_next) {                        // gmem prefetch overlaps compute
            na_h = *(const uint4*)(gAh + (s + 1) * 16);
            na_l = *(const uint4*)(gAl + (s + 1) * 16);
            nb_h = *(const uint4*)(gBh + (s + 1) * 16);
            nb_l = *(const uint4*)(gBl + (s + 1) * 16);
        }

        const char* st = smem + cur * HSTAGE;
        const uint16_t* sAh = (const uint16_t*)(st + HOFF_AH);
        const uint16_t* sAl = (const uint16_t*)(st + HOFF_AL);
        const uint16_t* sBh = (const uint16_t*)(st + HOFF_BH);
        const uint16_t* sBl = (const uint16_t*)(st + HOFF_BL);

        // A fragments (m16k16): regs = rows {g,g+8} x kcols {2t, 2t+8}
        uint32_t afh[4][4], afl[4][4];
#pragma unroll
        for (int mt = 0; mt < 4; ++mt) {
            int row = warp_m * 64 + mt * 16 + g;
            const uint16_t* ph = sAh + row * LDS_P;
            const uint16_t* pl = sAl + row * LDS_P;
            afh[mt][0] = *(const uint32_t*)(ph + 2 * t);
            afh[mt][1] = *(const uint32_t*)(ph + 8 * LDS_P + 2 * t);
            afh[mt][2] = *(const uint32_t*)(ph + 2 * t + 8);
            afh[mt][3] = *(const uint32_t*)(ph + 8 * LDS_P + 2 * t + 8);
            afl[mt][0] = *(const uint32_t*)(pl + 2 * t);
            afl[mt][1] = *(const uint32_t*)(pl + 8 * LDS_P + 2 * t);
            afl[mt][2] = *(const uint32_t*)(pl + 2 * t + 8);
            afl[mt][3] = *(const uint32_t*)(pl + 8 * LDS_P + 2 * t + 8);
        }
        // B fragments (k16n8 col-major == [n][k] row-major): b0 @ (n=g,k=2t)
        uint32_t bfh[4][2], bfl[4][2];
#pragma unroll
        for (int nt = 0; nt < 4; ++nt) {
            int n = warp_n * 32 + nt * 8 + g;
            const uint16_t* ph = sBh + n * LDS_P;
            const uint16_t* pl = sBl + n * LDS_P;
            bfh[nt][0] = *(const uint32_t*)(ph + 2 * t);
            bfh[nt][1] = *(const uint32_t*)(ph + 2 * t + 8);
            bfl[nt][0] = *(const uint32_t*)(pl + 2 * t);
            bfl[nt][1] = *(const uint32_t*)(pl + 2 * t + 8);
        }

#pragma unroll
        for (int mt = 0; mt < 4; ++mt)
#pragma unroll
            for (int nt = 0; nt < 4; ++nt) {
                mma16816(acc[mt][nt], afh[mt], bfh[nt]);
                mma16816(acc[mt][nt], afh[mt], bfl[nt]);
                mma16816(acc[mt][nt], afl[mt], bfh[nt]);
            }

        if (has_next) {
            char* nx = smem + (cur ^ 1) * HSTAGE;
            *(uint4*)(nx + HOFF_AH + sts_off) = na_h;
            *(uint4*)(nx + HOFF_AL + sts_off) = na_l;
            *(uint4*)(nx + HOFF_BH + sts_off) = nb_h;
            *(uint4*)(nx + HOFF_BL + sts_off) = nb_l;
            __syncthreads();
        }
    }

    // Epilogue: c0,c1 -> (row g, cols 2t,2t+1); c2,c3 -> (row g+8)
#pragma unroll
    for (int mt = 0; mt < 4; ++mt) {
        const int row = m0 + warp_m * 64 + mt * 16 + g;
#pragma unroll
        for (int nt = 0; nt < 4; ++nt) {
            const int c = n0 + warp_n * 32 + nt * 8 + 2 * t;
            float2 v0, v1;
            v0.x = acc[mt][nt][0]; v0.y = acc[mt][nt][1];
            v1.x = acc[mt][nt][2]; v1.y = acc[mt][nt][3];
            if (bias) {
                v0.x += bias[c]; v0.y += bias[c + 1];
                v1.x += bias[c]; v1.y += bias[c + 1];
            }
            *(float2*)&C[(size_t)row * N + c]       = v0;
            *(float2*)&C[(size_t)(row + 8) * N + c] = v1;
        }
    }
}

// ---------------------------------------------------------------------------
// Flash attention (UNCHANGED from the passing R6/R7 kernel).
// ---------------------------------------------------------------------------
#define SB 68
#define FLASH_SMEM (5 * 64 * SB * 4)

__global__ __launch_bounds__(256, 2)
void flash_kernel(float* __restrict__ O, const float* __restrict__ qkv)
{
    extern __shared__ float sm[];
    float* Qs  = sm;
    float* Ks  = sm + 1 * 64 * SB;
    float* Ps  = sm + 2 * 64 * SB;
    float* Vb0 = sm + 3 * 64 * SB;
    float* Vb1 = sm + 4 * 64 * SB;

    const int tid = threadIdx.x;
    const int tx = tid & 15;
    const int ty = tid >> 4;
    const int qb = (int)gridDim.x - 1 - (int)blockIdx.x;  // LPT: heavy first
    const int bh = blockIdx.y;
    const int b  = bh >> 4;
    const int h  = bh & 15;
    const int q0 = qb * 64;
    const int baseQ = (b * SEQ) * QKV_N + h * 192;
    const float scale = 1.0f / (float)HDIM;

#pragma unroll
    for (int it = 0; it < 4; ++it) {
        int idx = it * 256 + tid;
        int r = idx >> 4, c4 = (idx & 15) * 4;
        float4 v = *(const float4*)&qkv[baseQ + (q0 + r) * QKV_N + c4];
        v.x *= scale; v.y *= scale; v.z *= scale; v.w *= scale;
        *(float4*)&Qs[r * SB + c4] = v;
    }

    float4 kreg[4], vreg[4];
#pragma unroll
    for (int it = 0; it < 4; ++it) {
        int idx = it * 256 + tid;
        int r = idx >> 4, c4 = (idx & 15) * 4;
        int grow = baseQ + r * QKV_N;
        kreg[it] = *(const float4*)&qkv[grow + 64  + c4];
        vreg[it] = *(const float4*)&qkv[grow + 128 + c4];
    }
#pragma unroll
    for (int it = 0; it < 4; ++it) {
        int idx = it * 256 + tid;
        int r = idx >> 4, c4 = (idx & 15) * 4;
        *(float4*)&Ks [r * SB + c4] = kreg[it];
        *(float4*)&Vb0[r * SB + c4] = vreg[it];
    }
    __syncthreads();

    uint64_t accO2[4][2];
    float mprev[4], lprev[4];
#pragma unroll
    for (int i = 0; i < 4; ++i) {
        mprev[i] = -1e30f; lprev[i] = 0.f;
        accO2[i][0] = 0ull; accO2[i][1] = 0ull;
    }

    int vcur = 0;
    for (int jb = 0; jb <= qb; ++jb) {
        const bool has_next = (jb < qb);
        float* Vcur = vcur ? Vb1 : Vb0;
        float* Vnxt = vcur ? Vb0 : Vb1;

        if (has_next) {
#pragma unroll
            for (int it = 0; it < 4; ++it) {
                int idx = it * 256 + tid;
                int r = idx >> 4, c4 = (idx & 15) * 4;
                int grow = baseQ + ((jb + 1) * 64 + r) * QKV_N;
                kreg[it] = *(const float4*)&qkv[grow + 64  + c4];
                vreg[it] = *(const float4*)&qkv[grow + 128 + c4];
            }
        }

        uint64_t s2[4][4];
#pragma unroll
        for (int i = 0; i < 4; ++i)
#pragma unroll
            for (int j = 0; j < 4; ++j) s2[i][j] = 0ull;

#pragma unroll
        for (int d4 = 0; d4 < 16; ++d4) {
            float4 qv[4], kv[4];
#pragma unroll
            for (int i = 0; i < 4; ++i)
                qv[i] = *(const float4*)&Qs[(ty * 4 + i) * SB + d4 * 4];
#pragma unroll
            for (int j = 0; j < 4; ++j)
                kv[j] = *(const float4*)&Ks[(tx + 16 * j) * SB + d4 * 4];

            uint64_t qlo[4], qhi[4], klo[4], khi[4];
#pragma unroll
            for (int i = 0; i < 4; ++i) {
                qlo[i] = pk2(qv[i].x, qv[i].y);
                qhi[i] = pk2(qv[i].z, qv[i].w);
            }
#pragma unroll
            for (int j = 0; j < 4; ++j) {
                klo[j] = pk2(kv[j].x, kv[j].y);
                khi[j] = pk2(kv[j].z, kv[j].w);
            }
#pragma unroll
            for (int i = 0; i < 4; ++i)
#pragma unroll
                for (int j = 0; j < 4; ++j) {
                    fma2(s2[i][j], qlo[i], klo[j]);
                    fma2(s2[i][j], qhi[i], khi[j]);
                }
        }

        float sacc[4][4];
#pragma unroll
        for (int i = 0; i < 4; ++i)
#pragma unroll
            for (int j = 0; j < 4; ++j) {
                float2 f = upk2(s2[i][j]);
                sacc[i][j] = f.x + f.y;
            }

        if (jb == qb) {
#pragma unroll
            for (int i = 0; i < 4; ++i) {
                int rg = ty * 4 + i;
#pragma unroll
                for (int j = 0; j < 4; ++j)
                    if (tx + 16 * j > rg) sacc[i][j] = -1e30f;
            }
        }

#pragma unroll
        for (int i = 0; i < 4; ++i) {
            float mx = fmaxf(fmaxf(sacc[i][0], sacc[i][1]),
                             fmaxf(sacc[i][2], sacc[i][3]));
#pragma unroll
            for (int ofs = 1; ofs < 16; ofs <<= 1)
                mx = fmaxf(mx, __shfl_xor_sync(0xffffffffu, mx, ofs));
            float mnew = fmaxf(mprev[i], mx);
            float corr = __expf(mprev[i] - mnew);
            float s = 0.f;
#pragma unroll
            for (int j = 0; j < 4; ++j) {
                float p = __expf(sacc[i][j] - mnew);
                sacc[i][j] = p;
                s += p;
            }
#pragma unroll
            for (int ofs = 1; ofs < 16; ofs <<= 1)
                s += __shfl_xor_sync(0xffffffffu, s, ofs);
            lprev[i] = lprev[i] * corr + s;
            mprev[i] = mnew;
            uint64_t c2 = pk2(corr, corr);
            mul2(accO2[i][0], c2);
            mul2(accO2[i][1], c2);
        }

#pragma unroll
        for (int i = 0; i < 4; ++i)
#pragma unroll
            for (int j = 0; j < 4; ++j)
                Ps[(ty * 4 + i) * SB + tx + 16 * j] = sacc[i][j];
        __syncthreads();   // sync1

        if (has_next) {
#pragma unroll
            for (int it = 0; it < 4; ++it) {
                int idx = it * 256 + tid;
                int r = idx >> 4, c4 = (idx & 15) * 4;
                *(float4*)&Ks  [r * SB + c4] = kreg[it];
                *(float4*)&Vnxt[r * SB + c4] = vreg[it];
            }
        }

#pragma unroll
        for (int c4 = 0; c4 < 16; ++c4) {
            float4 pv[4], vv[4];
#pragma unroll
            for (int i = 0; i < 4; ++i)
                pv[i] = *(const float4*)&Ps[(ty * 4 + i) * SB + c4 * 4];
#pragma unroll
            for (int cc = 0; cc < 4; ++cc)
                vv[cc] = *(const float4*)&Vcur[(c4 * 4 + cc) * SB + tx * 4];

            uint64_t vlo[4], vhi[4];
#pragma unroll
            for (int cc = 0; cc < 4; ++cc) {
                vlo[cc] = pk2(vv[cc].x, vv[cc].y);
                vhi[cc] = pk2(vv[cc].z, vv[cc].w);
            }
#pragma unroll
            for (int i = 0; i < 4; ++i) {
                uint64_t p0 = pk2(pv[i].x, pv[i].x);
                uint64_t p1 = pk2(pv[i].y, pv[i].y);
                uint64_t p2 = pk2(pv[i].z, pv[i].z);
                uint64_t p3 = pk2(pv[i].w, pv[i].w);
                fma2(accO2[i][0], p0, vlo[0]); fma2(accO2[i][1], p0, vhi[0]);
                fma2(accO2[i][0], p1, vlo[1]); fma2(accO2[i][1], p1, vhi[1]);
                fma2(accO2[i][0], p2, vlo[2]); fma2(accO2[i][1], p2, vhi[2]);
                fma2(accO2[i][0], p3, vlo[3]); fma2(accO2[i][1], p3, vhi[3]);
            }
        }

        if (has_next) {
            __syncthreads();   // sync2
            vcur ^= 1;
        }
    }

#pragma unroll
    for (int i = 0; i < 4; ++i) {
        float inv = 1.0f / lprev[i];
        float2 lo = upk2(accO2[i][0]);
        float2 hi = upk2(accO2[i][1]);
        float4 o;
        o.x = lo.x * inv; o.y = lo.y * inv;
        o.z = hi.x * inv; o.w = hi.y * inv;
        int row = b * SEQ + q0 + ty * 4 + i;
        *(float4*)&O[row * DIM + h * HDIM + tx * 4] = o;
    }
}

// ---------------------------------------------------------------------------
extern "C" void kernel_launch(void* const* d_in, const int* in_sizes, int n_in,
                              void* d_out, int out_size)
{
    (void)in_sizes; (void)n_in; (void)out_size;
    const float* x     = (const float*)d_in[0];
    // d_in[1] = boolean causal mask (exactly tril; handled analytically)
    const float* w_qkv = (const float*)d_in[2];
    const float* w_out = (const float*)d_in[3];
    const float* b_out = (const float*)d_in[4];
    float* out = (float*)d_out;

    void *p_qkv, *p_attn, *p_xh, *p_xl, *p_ah, *p_al, *p_wqh, *p_wql, *p_woh, *p_wol;
    cudaGetSymbolAddress(&p_qkv,  g_qkv);
    cudaGetSymbolAddress(&p_attn, g_attn);
    cudaGetSymbolAddress(&p_xh,  g_xh);  cudaGetSymbolAddress(&p_xl,  g_xl);
    cudaGetSymbolAddress(&p_ah,  g_ah);  cudaGetSymbolAddress(&p_al,  g_al);
    cudaGetSymbolAddress(&p_wqh, g_wqh); cudaGetSymbolAddress(&p_wql, g_wql);
    cudaGetSymbolAddress(&p_woh, g_woh); cudaGetSymbolAddress(&p_wol, g_wol);
    float* qkv  = (float*)p_qkv;
    float* attn = (float*)p_attn;

    cudaFuncSetAttribute(flash_kernel,
                         cudaFuncAttributeMaxDynamicSharedMemorySize, FLASH_SMEM);
    cudaFuncSetAttribute(mma_hmma_bf16x3,
                         cudaFuncAttributeMaxDynamicSharedMemorySize, HMMA_SMEM);

    // 0) bf16 hi/lo splits of x and weights
    cvt_split<<<(MROWS * DIM / 4 + 255) / 256, 256>>>(
        x, (__nv_bfloat16*)p_xh, (__nv_bfloat16*)p_xl, MROWS * DIM / 4);
    cvt_split<<<(QKV_N * DIM / 4 + 255) / 256, 256>>>(
        w_qkv, (__nv_bfloat16*)p_wqh, (__nv_bfloat16*)p_wql, QKV_N * DIM / 4);
    cvt_split<<<(DIM * DIM / 4 + 255) / 256, 256>>>(
        w_out, (__nv_bfloat16*)p_woh, (__nv_bfloat16*)p_wol, DIM * DIM / 4);

    // 1) QKV projection via HMMA bf16x3: [4096,1024] @ [3072,1024]^T
    mma_hmma_bf16x3<<<dim3(QKV_N / 128, MROWS / 128), 256, HMMA_SMEM>>>(
        qkv, (const __nv_bfloat16*)p_xh, (const __nv_bfloat16*)p_xl,
        (const __nv_bfloat16*)p_wqh, (const __nv_bfloat16*)p_wql,
        nullptr, MROWS, QKV_N, DIM);

    // 2) Causal flash attention -> [4096,1024]
    flash_kernel<<<dim3(SEQ / 64, BATCH * HEADS), 256, FLASH_SMEM>>>(attn, qkv);

    // 3) Output projection via HMMA bf16x3 + bias
    cvt_split<<<(MROWS * DIM / 4 + 255) / 256, 256>>>(
        attn, (__nv_bfloat16*)p_ah, (__nv_bfloat16*)p_al, MROWS * DIM / 4);
    mma_hmma_bf16x3<<<dim3(DIM / 128, MROWS / 128), 256, HMMA_SMEM>>>(
        out, (const __nv_bfloat16*)p_ah, (const __nv_bfloat16*)p_al,
        (const __nv_bfloat16*)p_woh, (const __nv_bfloat16*)p_wol,
        b_out, MROWS, DIM, DIM);
}

// round 17
// speedup vs baseline: 1.3420x; 1.1789x over previous
#include <cuda_runtime.h>
#include <cuda_bf16.h>
#include <cstdint>

// Problem constants
#define BATCH 2
#define SEQ   2048
#define DIM   1024
#define HEADS 16
#define HDIM  64
#define MROWS (BATCH * SEQ)          // 4096
#define QKV_N (3 * DIM)              // 3072

// Scratch (allocation-free rule: __device__ globals)
__device__ float g_qkv [MROWS * QKV_N];   // fp32 qkv for flash
__device__ float g_attn[MROWS * DIM];     // fp32 attention output
// bf16x3 split operands
__device__ __nv_bfloat16 g_xh [MROWS * DIM],  g_xl [MROWS * DIM];
__device__ __nv_bfloat16 g_ah [MROWS * DIM],  g_al [MROWS * DIM];
__device__ __nv_bfloat16 g_wqh[QKV_N * DIM],  g_wql[QKV_N * DIM];
__device__ __nv_bfloat16 g_woh[DIM * DIM],    g_wol[DIM * DIM];

// ---- packed fp32x2 helpers (FFMA2 path for flash; base-target legal) -------
__device__ __forceinline__ uint64_t pk2(float lo, float hi) {
    uint64_t r; asm("mov.b64 %0, {%1, %2};" : "=l"(r) : "f"(lo), "f"(hi)); return r;
}
__device__ __forceinline__ float2 upk2(uint64_t v) {
    float2 f; asm("mov.b64 {%0, %1}, %2;" : "=f"(f.x), "=f"(f.y) : "l"(v)); return f;
}
__device__ __forceinline__ void fma2(uint64_t& d, uint64_t a, uint64_t b) {
    asm("fma.rn.f32x2 %0, %1, %2, %0;" : "+l"(d) : "l"(a), "l"(b));
}
__device__ __forceinline__ void mul2(uint64_t& d, uint64_t c) {
    asm("mul.rn.f32x2 %0, %0, %1;" : "+l"(d) : "l"(c));
}

// ---- warp-level bf16 HMMA (sm_80-era PTX, valid on compute_103 base) -------
__device__ __forceinline__ void mma16816(float* d, const uint32_t* a,
                                         const uint32_t* b) {
    asm volatile(
        "mma.sync.aligned.m16n8k16.row.col.f32.bf16.bf16.f32 "
        "{%0,%1,%2,%3}, {%4,%5,%6,%7}, {%8,%9}, {%0,%1,%2,%3};"
        : "+f"(d[0]), "+f"(d[1]), "+f"(d[2]), "+f"(d[3])
        : "r"(a[0]), "r"(a[1]), "r"(a[2]), "r"(a[3]), "r"(b[0]), "r"(b[1]));
}

// ===================== fp32 -> bf16 hi/lo split =============================
__global__ void cvt_split(const float* __restrict__ x,
                          __nv_bfloat16* __restrict__ hi,
                          __nv_bfloat16* __restrict__ lo, int n4)
{
    int i = blockIdx.x * blockDim.x + threadIdx.x;
    if (i >= n4) return;
    float4 v = ((const float4*)x)[i];
    __nv_bfloat16 h0 = __float2bfloat16(v.x);
    __nv_bfloat16 h1 = __float2bfloat16(v.y);
    __nv_bfloat16 h2 = __float2bfloat16(v.z);
    __nv_bfloat16 h3 = __float2bfloat16(v.w);
    __nv_bfloat16 l0 = __float2bfloat16(v.x - __bfloat162float(h0));
    __nv_bfloat16 l1 = __float2bfloat16(v.y - __bfloat162float(h1));
    __nv_bfloat16 l2 = __float2bfloat16(v.z - __bfloat162float(h2));
    __nv_bfloat16 l3 = __float2bfloat16(v.w - __bfloat162float(h3));
    ((__nv_bfloat162*)hi)[2*i]   = __nv_bfloat162(h0, h1);
    ((__nv_bfloat162*)hi)[2*i+1] = __nv_bfloat162(h2, h3);
    ((__nv_bfloat162*)lo)[2*i]   = __nv_bfloat162(l0, l1);
    ((__nv_bfloat162*)lo)[2*i+1] = __nv_bfloat162(l2, l3);
}

// ===================== HMMA bf16x3 GEMM =====================================
// C[M,N] = (Ah+Al)[M,K] @ (Bh+Bl)[N,K]^T (+ bias); fp32 accum of
// AhBh + AhBl + AlBh. Block tile 128x128x16, 8 warps (2x4), warp tile 64x32.
// Smem: Ah|Al|Bh|Bl tiles, 128 rows x 16 k at padded stride 24 elements,
// double-buffered. A fragments are loaded per-mt inside the MMA loop (register
// diet) and __launch_bounds__(256,2) pins 2 CTAs/SM — the R16 profile showed
// occ=12.4%/issue=14.1% (latency-bound at 1 CTA/SM, regs=147).
#define LDS_P  24                                 // padded stride (elements)
#define MAT_B  (128 * LDS_P * 2)                  // bytes per matrix tile: 6144
#define HOFF_AH 0
#define HOFF_AL (1 * MAT_B)
#define HOFF_BH (2 * MAT_B)
#define HOFF_BL (3 * MAT_B)
#define HSTAGE  (4 * MAT_B)                       // 24576 B per stage
#define HMMA_SMEM (2 * HSTAGE)                    // 49152 B

__global__ __launch_bounds__(256, 2)
void mma_hmma_bf16x3(float* __restrict__ C,
                     const __nv_bfloat16* __restrict__ Ah,
                     const __nv_bfloat16* __restrict__ Al,
                     const __nv_bfloat16* __restrict__ Bh,
                     const __nv_bfloat16* __restrict__ Bl,
                     const float* __restrict__ bias,
                     int M, int N, int K)
{
    extern __shared__ char smem[];
    const int tid = threadIdx.x;
    const int wid = tid >> 5;
    const int lane = tid & 31;
    const int g = lane >> 2;          // 0..7
    const int t = lane & 3;           // 0..3
    const int warp_m = wid & 1;       // 2 warps along M (64 rows each)
    const int warp_n = wid >> 1;      // 4 warps along N (32 cols each)
    const int m0 = blockIdx.y * 128;
    const int n0 = blockIdx.x * 128;

    // Loader coords: r = tid>>1 (0..127), kc = (tid&1)*8 (half-row of 8 bf16)
    const int lr = tid >> 1;
    const int lkc = (tid & 1) * 8;
    const __nv_bfloat16* gAh = Ah + (size_t)(m0 + lr) * K + lkc;
    const __nv_bfloat16* gAl = Al + (size_t)(m0 + lr) * K + lkc;
    const __nv_bfloat16* gBh = Bh + (size_t)(n0 + lr) * K + lkc;
    const __nv_bfloat16* gBl = Bl + (size_t)(n0 + lr) * K + lkc;
    const uint32_t sts_off = (uint32_t)(lr * LDS_P + lkc) * 2;  // bytes

    // Stage 0 fill
    {
        uint4 va_h = *(const uint4*)gAh;
        uint4 va_l = *(const uint4*)gAl;
        uint4 vb_h = *(const uint4*)gBh;
        uint4 vb_l = *(const uint4*)gBl;
        *(uint4*)(smem + HOFF_AH + sts_off) = va_h;
        *(uint4*)(smem + HOFF_AL + sts_off) = va_l;
        *(uint4*)(smem + HOFF_BH + sts_off) = vb_h;
        *(uint4*)(smem + HOFF_BL + sts_off) = vb_l;
    }
    __syncthreads();

    float acc[4][4][4];               // [mt][nt][c0..c3]
#pragma unroll
    for (int mt = 0; mt < 4; ++mt)
#pragma unroll
        for (int nt = 0; nt < 4; ++nt)
#pragma unroll
            for (int c = 0; c < 4; ++c) acc[mt][nt][c] = 0.f;

    const int NS = K / 16;
    for (int s = 0; s < NS; ++s) {
        const int cur = s & 1;
        const bool has_next = (s + 1 < NS);
        uint4 na_h, na_l, nb_h, nb_l;
        if (has_next) {                        // gmem prefetch overlaps compute
            na_h = *(const uint4*)(gAh + (s + 1) * 16);
            na_l = *(const uint4*)(gAl + (s + 1) * 16);
            nb_h = *(const uint4*)(gBh + (s + 1) * 16);
            nb_l = *(const uint4*)(gBl + (s + 1) * 16);
        }

        const char* st = smem + cur * HSTAGE;
        const uint16_t* sAh = (const uint16_t*)(st + HOFF_AH);
        const uint16_t* sAl = (const uint16_t*)(st + HOFF_AL);
        const uint16_t* sBh = (const uint16_t*)(st + HOFF_BH);
        const uint16_t* sBl = (const uint16_t*)(st + HOFF_BL);

        // B fragments (k16n8, [n][k] storage): b0 @ (n=g,k=2t), b1 @ k=2t+8
        uint32_t bfh[4][2], bfl[4][2];
#pragma unroll
        for (int nt = 0; nt < 4; ++nt) {
            int n = warp_n * 32 + nt * 8 + g;
            const uint16_t* ph = sBh + n * LDS_P;
            const uint16_t* pl = sBl + n * LDS_P;
            bfh[nt][0] = *(const uint32_t*)(ph + 2 * t);
            bfh[nt][1] = *(const uint32_t*)(ph + 2 * t + 8);
            bfl[nt][0] = *(const uint32_t*)(pl + 2 * t);
            bfl[nt][1] = *(const uint32_t*)(pl + 2 * t + 8);
        }

        // A fragments loaded per-mt (8 live regs instead of 32)
#pragma unroll
        for (int mt = 0; mt < 4; ++mt) {
            int row = warp_m * 64 + mt * 16 + g;
            const uint16_t* ph = sAh + row * LDS_P;
            const uint16_t* pl = sAl + row * LDS_P;
            uint32_t afh[4], afl[4];
            afh[0] = *(const uint32_t*)(ph + 2 * t);
            afh[1] = *(const uint32_t*)(ph + 8 * LDS_P + 2 * t);
            afh[2] = *(const uint32_t*)(ph + 2 * t + 8);
            afh[3] = *(const uint32_t*)(ph + 8 * LDS_P + 2 * t + 8);
            afl[0] = *(const uint32_t*)(pl + 2 * t);
            afl[1] = *(const uint32_t*)(pl + 8 * LDS_P + 2 * t);
            afl[2] = *(const uint32_t*)(pl + 2 * t + 8);
            afl[3] = *(const uint32_t*)(pl + 8 * LDS_P + 2 * t + 8);
#pragma unroll
            for (int nt = 0; nt < 4; ++nt) {
                mma16816(acc[mt][nt], afh, bfh[nt]);
                mma16816(acc[mt][nt], afh, bfl[nt]);
                mma16816(acc[mt][nt], afl, bfh[nt]);
            }
        }

        if (has_next) {
            char* nx = smem + (cur ^ 1) * HSTAGE;
            *(uint4*)(nx + HOFF_AH + sts_off) = na_h;
            *(uint4*)(nx + HOFF_AL + sts_off) = na_l;
            *(uint4*)(nx + HOFF_BH + sts_off) = nb_h;
            *(uint4*)(nx + HOFF_BL + sts_off) = nb_l;
            __syncthreads();
        }
    }

    // Epilogue: c0,c1 -> (row g, cols 2t,2t+1); c2,c3 -> (row g+8)
#pragma unroll
    for (int mt = 0; mt < 4; ++mt) {
        const int row = m0 + warp_m * 64 + mt * 16 + g;
#pragma unroll
        for (int nt = 0; nt < 4; ++nt) {
            const int c = n0 + warp_n * 32 + nt * 8 + 2 * t;
            float2 v0, v1;
            v0.x = acc[mt][nt][0]; v0.y = acc[mt][nt][1];
            v1.x = acc[mt][nt][2]; v1.y = acc[mt][nt][3];
            if (bias) {
                v0.x += bias[c]; v0.y += bias[c + 1];
                v1.x += bias[c]; v1.y += bias[c + 1];
            }
            *(float2*)&C[(size_t)row * N + c]       = v0;
            *(float2*)&C[(size_t)(row + 8) * N + c] = v1;
        }
    }
}

// ---------------------------------------------------------------------------
// Flash attention (UNCHANGED from the passing kernel).
// ---------------------------------------------------------------------------
#define SB 68
#define FLASH_SMEM (5 * 64 * SB * 4)

__global__ __launch_bounds__(256, 2)
void flash_kernel(float* __restrict__ O, const float* __restrict__ qkv)
{
    extern __shared__ float sm[];
    float* Qs  = sm;
    float* Ks  = sm + 1 * 64 * SB;
    float* Ps  = sm + 2 * 64 * SB;
    float* Vb0 = sm + 3 * 64 * SB;
    float* Vb1 = sm + 4 * 64 * SB;

    const int tid = threadIdx.x;
    const int tx = tid & 15;
    const int ty = tid >> 4;
    const int qb = (int)gridDim.x - 1 - (int)blockIdx.x;  // LPT: heavy first
    const int bh = blockIdx.y;
    const int b  = bh >> 4;
    const int h  = bh & 15;
    const int q0 = qb * 64;
    const int baseQ = (b * SEQ) * QKV_N + h * 192;
    const float scale = 1.0f / (float)HDIM;

#pragma unroll
    for (int it = 0; it < 4; ++it) {
        int idx = it * 256 + tid;
        int r = idx >> 4, c4 = (idx & 15) * 4;
        float4 v = *(const float4*)&qkv[baseQ + (q0 + r) * QKV_N + c4];
        v.x *= scale; v.y *= scale; v.z *= scale; v.w *= scale;
        *(float4*)&Qs[r * SB + c4] = v;
    }

    float4 kreg[4], vreg[4];
#pragma unroll
    for (int it = 0; it < 4; ++it) {
        int idx = it * 256 + tid;
        int r = idx >> 4, c4 = (idx & 15) * 4;
        int grow = baseQ + r * QKV_N;
        kreg[it] = *(const float4*)&qkv[grow + 64  + c4];
        vreg[it] = *(const float4*)&qkv[grow + 128 + c4];
    }
#pragma unroll
    for (int it = 0; it < 4; ++it) {
        int idx = it * 256 + tid;
        int r = idx >> 4, c4 = (idx & 15) * 4;
        *(float4*)&Ks [r * SB + c4] = kreg[it];
        *(float4*)&Vb0[r * SB + c4] = vreg[it];
    }
    __syncthreads();

    uint64_t accO2[4][2];
    float mprev[4], lprev[4];
#pragma unroll
    for (int i = 0; i < 4; ++i) {
        mprev[i] = -1e30f; lprev[i] = 0.f;
        accO2[i][0] = 0ull; accO2[i][1] = 0ull;
    }

    int vcur = 0;
    for (int jb = 0; jb <= qb; ++jb) {
        const bool has_next = (jb < qb);
        float* Vcur = vcur ? Vb1 : Vb0;
        float* Vnxt = vcur ? Vb0 : Vb1;

        if (has_next) {
#pragma unroll
            for (int it = 0; it < 4; ++it) {
                int idx = it * 256 + tid;
                int r = idx >> 4, c4 = (idx & 15) * 4;
                int grow = baseQ + ((jb + 1) * 64 + r) * QKV_N;
                kreg[it] = *(const float4*)&qkv[grow + 64  + c4];
                vreg[it] = *(const float4*)&qkv[grow + 128 + c4];
            }
        }

        uint64_t s2[4][4];
#pragma unroll
        for (int i = 0; i < 4; ++i)
#pragma unroll
            for (int j = 0; j < 4; ++j) s2[i][j] = 0ull;

#pragma unroll
        for (int d4 = 0; d4 < 16; ++d4) {
            float4 qv[4], kv[4];
#pragma unroll
            for (int i = 0; i < 4; ++i)
                qv[i] = *(const float4*)&Qs[(ty * 4 + i) * SB + d4 * 4];
#pragma unroll
            for (int j = 0; j < 4; ++j)
                kv[j] = *(const float4*)&Ks[(tx + 16 * j) * SB + d4 * 4];

            uint64_t qlo[4], qhi[4], klo[4], khi[4];
#pragma unroll
            for (int i = 0; i < 4; ++i) {
                qlo[i] = pk2(qv[i].x, qv[i].y);
                qhi[i] = pk2(qv[i].z, qv[i].w);
            }
#pragma unroll
            for (int j = 0; j < 4; ++j) {
                klo[j] = pk2(kv[j].x, kv[j].y);
                khi[j] = pk2(kv[j].z, kv[j].w);
            }
#pragma unroll
            for (int i = 0; i < 4; ++i)
#pragma unroll
                for (int j = 0; j < 4; ++j) {
                    fma2(s2[i][j], qlo[i], klo[j]);
                    fma2(s2[i][j], qhi[i], khi[j]);
                }
        }

        float sacc[4][4];
#pragma unroll
        for (int i = 0; i < 4; ++i)
#pragma unroll
            for (int j = 0; j < 4; ++j) {
                float2 f = upk2(s2[i][j]);
                sacc[i][j] = f.x + f.y;
            }

        if (jb == qb) {
#pragma unroll
            for (int i = 0; i < 4; ++i) {
                int rg = ty * 4 + i;
#pragma unroll
                for (int j = 0; j < 4; ++j)
                    if (tx + 16 * j > rg) sacc[i][j] = -1e30f;
            }
        }

#pragma unroll
        for (int i = 0; i < 4; ++i) {
            float mx = fmaxf(fmaxf(sacc[i][0], sacc[i][1]),
                             fmaxf(sacc[i][2], sacc[i][3]));
#pragma unroll
            for (int ofs = 1; ofs < 16; ofs <<= 1)
                mx = fmaxf(mx, __shfl_xor_sync(0xffffffffu, mx, ofs));
            float mnew = fmaxf(mprev[i], mx);
            float corr = __expf(mprev[i] - mnew);
            float s = 0.f;
#pragma unroll
            for (int j = 0; j < 4; ++j) {
                float p = __expf(sacc[i][j] - mnew);
                sacc[i][j] = p;
                s += p;
            }
#pragma unroll
            for (int ofs = 1; ofs < 16; ofs <<= 1)
                s += __shfl_xor_sync(0xffffffffu, s, ofs);
            lprev[i] = lprev[i] * corr + s;
            mprev[i] = mnew;
            uint64_t c2 = pk2(corr, corr);
            mul2(accO2[i][0], c2);
            mul2(accO2[i][1], c2);
        }

#pragma unroll
        for (int i = 0; i < 4; ++i)
#pragma unroll
            for (int j = 0; j < 4; ++j)
                Ps[(ty * 4 + i) * SB + tx + 16 * j] = sacc[i][j];
        __syncthreads();   // sync1

        if (has_next) {
#pragma unroll
            for (int it = 0; it < 4; ++it) {
                int idx = it * 256 + tid;
                int r = idx >> 4, c4 = (idx & 15) * 4;
                *(float4*)&Ks  [r * SB + c4] = kreg[it];
                *(float4*)&Vnxt[r * SB + c4] = vreg[it];
            }
        }

#pragma unroll
        for (int c4 = 0; c4 < 16; ++c4) {
            float4 pv[4], vv[4];
#pragma unroll
            for (int i = 0; i < 4; ++i)
                pv[i] = *(const float4*)&Ps[(ty * 4 + i) * SB + c4 * 4];
#pragma unroll
            for (int cc = 0; cc < 4; ++cc)
                vv[cc] = *(const float4*)&Vcur[(c4 * 4 + cc) * SB + tx * 4];

            uint64_t vlo[4], vhi[4];
#pragma unroll
            for (int cc = 0; cc < 4; ++cc) {
                vlo[cc] = pk2(vv[cc].x, vv[cc].y);
                vhi[cc] = pk2(vv[cc].z, vv[cc].w);
            }
#pragma unroll
            for (int i = 0; i < 4; ++i) {
                uint64_t p0 = pk2(pv[i].x, pv[i].x);
                uint64_t p1 = pk2(pv[i].y, pv[i].y);
                uint64_t p2 = pk2(pv[i].z, pv[i].z);
                uint64_t p3 = pk2(pv[i].w, pv[i].w);
                fma2(accO2[i][0], p0, vlo[0]); fma2(accO2[i][1], p0, vhi[0]);
                fma2(accO2[i][0], p1, vlo[1]); fma2(accO2[i][1], p1, vhi[1]);
                fma2(accO2[i][0], p2, vlo[2]); fma2(accO2[i][1], p2, vhi[2]);
                fma2(accO2[i][0], p3, vlo[3]); fma2(accO2[i][1], p3, vhi[3]);
            }
        }

        if (has_next) {
            __syncthreads();   // sync2
            vcur ^= 1;
        }
    }

#pragma unroll
    for (int i = 0; i < 4; ++i) {
        float inv = 1.0f / lprev[i];
        float2 lo = upk2(accO2[i][0]);
        float2 hi = upk2(accO2[i][1]);
        float4 o;
        o.x = lo.x * inv; o.y = lo.y * inv;
        o.z = hi.x * inv; o.w = hi.y * inv;
        int row = b * SEQ + q0 + ty * 4 + i;
        *(float4*)&O[row * DIM + h * HDIM + tx * 4] = o;
    }
}

// ---------------------------------------------------------------------------
extern "C" void kernel_launch(void* const* d_in, const int* in_sizes, int n_in,
                              void* d_out, int out_size)
{
    (void)in_sizes; (void)n_in; (void)out_size;
    const float* x     = (const float*)d_in[0];
    // d_in[1] = boolean causal mask (exactly tril; handled analytically)
    const float* w_qkv = (const float*)d_in[2];
    const float* w_out = (const float*)d_in[3];
    const float* b_out = (const float*)d_in[4];
    float* out = (float*)d_out;

    void *p_qkv, *p_attn, *p_xh, *p_xl, *p_ah, *p_al, *p_wqh, *p_wql, *p_woh, *p_wol;
    cudaGetSymbolAddress(&p_qkv,  g_qkv);
    cudaGetSymbolAddress(&p_attn, g_attn);
    cudaGetSymbolAddress(&p_xh,  g_xh);  cudaGetSymbolAddress(&p_xl,  g_xl);
    cudaGetSymbolAddress(&p_ah,  g_ah);  cudaGetSymbolAddress(&p_al,  g_al);
    cudaGetSymbolAddress(&p_wqh, g_wqh); cudaGetSymbolAddress(&p_wql, g_wql);
    cudaGetSymbolAddress(&p_woh, g_woh); cudaGetSymbolAddress(&p_wol, g_wol);
    float* qkv  = (float*)p_qkv;
    float* attn = (float*)p_attn;

    cudaFuncSetAttribute(flash_kernel,
                         cudaFuncAttributeMaxDynamicSharedMemorySize, FLASH_SMEM);
    cudaFuncSetAttribute(mma_hmma_bf16x3,
                         cudaFuncAttributeMaxDynamicSharedMemorySize, HMMA_SMEM);

    // 0) bf16 hi/lo splits of x and weights
    cvt_split<<<(MROWS * DIM / 4 + 255) / 256, 256>>>(
        x, (__nv_bfloat16*)p_xh, (__nv_bfloat16*)p_xl, MROWS * DIM / 4);
    cvt_split<<<(QKV_N * DIM / 4 + 255) / 256, 256>>>(
        w_qkv, (__nv_bfloat16*)p_wqh, (__nv_bfloat16*)p_wql, QKV_N * DIM / 4);
    cvt_split<<<(DIM * DIM / 4 + 255) / 256, 256>>>(
        w_out, (__nv_bfloat16*)p_woh, (__nv_bfloat16*)p_wol, DIM * DIM / 4);

    // 1) QKV projection via HMMA bf16x3: [4096,1024] @ [3072,1024]^T
    mma_hmma_bf16x3<<<dim3(QKV_N / 128, MROWS / 128), 256, HMMA_SMEM>>>(
        qkv, (const __nv_bfloat16*)p_xh, (const __nv_bfloat16*)p_xl,
        (const __nv_bfloat16*)p_wqh, (const __nv_bfloat16*)p_wql,
        nullptr, MROWS, QKV_N, DIM);

    // 2) Causal flash attention -> [4096,1024]
    flash_kernel<<<dim3(SEQ / 64, BATCH * HEADS), 256, FLASH_SMEM>>>(attn, qkv);

    // 3) Output projection via HMMA bf16x3 + bias
    cvt_split<<<(MROWS * DIM / 4 + 255) / 256, 256>>>(
        attn, (__nv_bfloat16*)p_ah, (__nv_bfloat16*)p_al, MROWS * DIM / 4);
    mma_hmma_bf16x3<<<dim3(DIM / 128, MROWS / 128), 256, HMMA_SMEM>>>(
        out, (const __nv_bfloat16*)p_ah, (const __nv_bfloat16*)p_al,
        (const __nv_bfloat16*)p_woh, (const __nv_bfloat16*)p_wol,
        b_out, MROWS, DIM, DIM);
}